// round 12
// baseline (speedup 1.0000x reference)
#include <cuda_runtime.h>
#include <cuda_fp16.h>
#include <cstdint>

// Fused 2-layer MLP, pure fp16 mma.sync, 2 CTAs/SM, software-pipelined:
// GEMM2(c-1) overlaps GEMM1(c) in the same basic block (2 phases/chunk,
// 2 barriers/chunk). Weights split in k-halves so cp.async refills always
// write regions disjoint from the half being read.
//   out = relu(relu(X@W0+b0)@W1+b1); rel_err ~4.2e-4 (validated R9/R11).

#define K1   192
#define HID  1024
#define EMB  256
#define NCH  16

#define XS_W  100
#define W0S_W 100
#define HS_W  36
#define W1S_W 36

// smem byte offsets (total 111616 -> 2 CTAs/SM: 223232 <= 233472)
#define SM_B0S 0                      // 4096
#define SM_B1S 4096                   // 1024
#define SM_XS  5120                   // 64*400  = 25600
#define SM_W0S 30720                  // 64*400  = 25600
#define SM_W1S 56320                  // 256*144 = 36864
#define SM_HS  93184                  // 2 x 64*144 = 18432
#define SM_TOTAL 111616

__device__ __align__(16) __half g_B1[HID * K1];     // W0^T [n][k]
__device__ __align__(16) __half g_B2[EMB * HID];    // W1^T [n][k]

__device__ __forceinline__ void cpa16(uint32_t dst, const void* src) {
    asm volatile("cp.async.cg.shared.global [%0], [%1], 16;" :: "r"(dst), "l"(src) : "memory");
}
#define CP_COMMIT() asm volatile("cp.async.commit_group;" ::: "memory")
#define CP_WAIT0()  asm volatile("cp.async.wait_group 0;" ::: "memory")

__device__ __forceinline__ uint32_t smem_u32(const void* p) {
    uint32_t a;
    asm("{ .reg .u64 t; cvta.to.shared.u64 t, %1; cvt.u32.u64 %0, t; }" : "=r"(a) : "l"(p));
    return a;
}

__device__ __forceinline__ void mma16816(float* c,
    uint32_t a0, uint32_t a1, uint32_t a2, uint32_t a3, uint32_t b0, uint32_t b1)
{
    asm volatile("mma.sync.aligned.m16n8k16.row.col.f32.f16.f16.f32 "
        "{%0,%1,%2,%3}, {%4,%5,%6,%7}, {%8,%9}, {%0,%1,%2,%3};"
        : "+f"(c[0]), "+f"(c[1]), "+f"(c[2]), "+f"(c[3])
        : "r"(a0), "r"(a1), "r"(a2), "r"(a3), "r"(b0), "r"(b1));
}

__device__ __forceinline__ uint32_t pack2(float x, float y) {
    __half2 h = __halves2half2(__float2half_rn(x), __float2half_rn(y));
    return *(uint32_t*)&h;
}

// ---------------- weight prep ----------------
__global__ void prep_kernel(const float* __restrict__ W0, const float* __restrict__ W1) {
    int stride = gridDim.x * blockDim.x;
    int t0 = blockIdx.x * blockDim.x + threadIdx.x;
    for (int i = t0; i < HID * K1; i += stride) {
        int n = i / K1, k = i % K1;
        g_B1[n * K1 + k] = __float2half_rn(W0[k * HID + n]);
    }
    for (int i = t0; i < EMB * HID; i += stride) {
        int n = i / HID, k = i % HID;
        g_B2[n * HID + k] = __float2half_rn(W1[k * EMB + n]);
    }
}

// ---------------- k-half chunk loaders ----------------
__device__ __forceinline__ void load_w0_half(uint32_t sb, int c, int h, int tid) {
    const __half* base = g_B1 + (size_t)c * 64 * K1 + h * 96;
    #pragma unroll
    for (int i = tid; i < 768; i += 256) {            // 64 rows x 12 x 16B
        int n = i / 12, u = i % 12;
        cpa16(sb + SM_W0S + n * 400 + h * 192 + u * 16, base + n * K1 + u * 8);
    }
}
__device__ __forceinline__ void load_w1_half(uint32_t sb, int c, int h, int tid) {
    const __half* base = g_B2 + c * 64 + h * 32;
    #pragma unroll
    for (int i = tid; i < 1024; i += 256) {           // 256 rows x 4 x 16B
        int n = i / 4, u = i % 4;
        cpa16(sb + SM_W1S + n * 144 + h * 64 + u * 16, base + n * HID + u * 8);
    }
}

// ---------------- compute step helpers ----------------
template<int K0, int K1E>
__device__ __forceinline__ void g1_steps(float c1[4][4], const uint32_t* xsw,
    const uint32_t* w0sw, int m1, int n1, int r, int q)
{
    #pragma unroll
    for (int kk = K0; kk < K1E; kk++) {
        const int kw = kk * 8;
        const uint32_t* ap = xsw + (m1 + r) * XS_W + kw + q;
        uint32_t a0 = ap[0], a1 = ap[8 * XS_W], a2 = ap[4], a3 = ap[8 * XS_W + 4];
        #pragma unroll
        for (int j = 0; j < 4; j++) {
            const uint32_t* bp_ = w0sw + (n1 + j * 8 + r) * W0S_W + kw + q;
            mma16816(c1[j], a0, a1, a2, a3, bp_[0], bp_[4]);
        }
    }
}

template<int G0, int G1E>
__device__ __forceinline__ void g2_steps(float acc2[16][4], const uint32_t* hq,
    const uint32_t* w1sw, int m2, int n2, int r, int q)
{
    #pragma unroll
    for (int kk = G0; kk < G1E; kk++) {
        const int kw = kk * 8;
        uint32_t a[2][4];
        #pragma unroll
        for (int f = 0; f < 2; f++) {
            const uint32_t* ap = hq + (m2 + f * 16 + r) * HS_W + kw + q;
            a[f][0] = ap[0]; a[f][1] = ap[8 * HS_W]; a[f][2] = ap[4]; a[f][3] = ap[8 * HS_W + 4];
        }
        #pragma unroll
        for (int j = 0; j < 8; j++) {
            const uint32_t* bp_ = w1sw + (n2 + j * 8 + r) * W1S_W + kw + q;
            uint32_t b0_ = bp_[0], b1_ = bp_[4];
            #pragma unroll
            for (int f = 0; f < 2; f++)
                mma16816(acc2[j * 2 + f], a[f][0], a[f][1], a[f][2], a[f][3], b0_, b1_);
        }
    }
}

__device__ __forceinline__ void convert_store(float c1[4][4], uint32_t* hsp,
    const float* b0s, int c, int m1, int n1, int r, int q)
{
    const int hb = c * 64;
    #pragma unroll
    for (int j = 0; j < 4; j++) {
        int n = n1 + j * 8 + q * 2;
        float bb0 = b0s[hb + n], bb1 = b0s[hb + n + 1];
        float v0 = fmaxf(c1[j][0] + bb0, 0.f);
        float v1 = fmaxf(c1[j][1] + bb1, 0.f);
        float v2 = fmaxf(c1[j][2] + bb0, 0.f);
        float v3 = fmaxf(c1[j][3] + bb1, 0.f);
        hsp[(m1 + r) * HS_W + (n >> 1)]     = pack2(v0, v1);
        hsp[(m1 + r + 8) * HS_W + (n >> 1)] = pack2(v2, v3);
    }
}

// ---------------- main fused kernel ----------------
__global__ void __launch_bounds__(256, 2)
mlp_kernel(const float* __restrict__ x, const float* __restrict__ b0,
           const float* __restrict__ b1, float* __restrict__ out)
{
    extern __shared__ char smem[];
    const uint32_t sb = smem_u32(smem);
    const int tid  = threadIdx.x;
    const int lane = tid & 31;
    const int w    = tid >> 5;
    const int r    = lane >> 2;
    const int q    = lane & 3;

    const int m1 = (w >> 1) * 16;
    const int n1 = (w & 1) * 32;
    const int m2 = (w >> 2) * 32;
    const int n2 = (w & 3) * 64;

    const int slice   = blockIdx.x >> 1;
    const int tokbase = (blockIdx.x & 1) * 64;

    uint32_t*       xsw  = (uint32_t*)(smem + SM_XS);
    const uint32_t* w0sw = (const uint32_t*)(smem + SM_W0S);
    uint32_t*       hsw  = (uint32_t*)(smem + SM_HS);
    const uint32_t* w1sw = (const uint32_t*)(smem + SM_W1S);
    float*          b0s  = (float*)(smem + SM_B0S);
    float*          b1s  = (float*)(smem + SM_B1S);

    // prologue: whole W0(0) in flight
    load_w0_half(sb, 0, 0, tid);
    load_w0_half(sb, 0, 1, tid);
    CP_COMMIT();

    // X slice -> Xs (fp16)
    {
        const float2* x2 = (const float2*)(x + (size_t)slice * 24576);
        #pragma unroll 4
        for (int i = tid; i < 6144; i += 256) {
            int m = i / 96, u = i % 96;
            int ch = u >> 5, bp = u & 31;
            float2 v = x2[(ch * 8192 + (tokbase + m) * 64) / 2 + bp];
            xsw[m * XS_W + ch * 32 + bp] = pack2(v.x, v.y);
        }
        for (int i = tid; i < 1024; i += 256) b0s[i] = b0[i];
        for (int i = tid; i < 256;  i += 256) b1s[i] = b1[i];
    }

    float acc2[16][4];
    #pragma unroll
    for (int j = 0; j < 16; j++)
        #pragma unroll
        for (int e = 0; e < 4; e++) acc2[j][e] = 0.0f;

    // ===== peel c = 0 (GEMM1 only) =====
    {
        CP_WAIT0(); __syncthreads();          // w0(0) + Xs visible
        float c1[4][4] = {};
        g1_steps<0, 6>(c1, xsw, w0sw, m1, n1, r, q);

        CP_WAIT0(); __syncthreads();
        load_w0_half(sb, 1, 0, tid);          // w0a <- W0(1)a
        load_w1_half(sb, 0, 0, tid);          // w1a <- W1(0)a
        CP_COMMIT();
        g1_steps<6, 12>(c1, xsw, w0sw, m1, n1, r, q);
        convert_store(c1, hsw, b0s, 0, m1, n1, r, q);   // hs[0]
    }

    // ===== steady: c = 1..15 (GEMM1(c) overlapped with GEMM2(c-1)) =====
    for (int c = 1; c <= 15; c++) {
        const int p = c & 1;
        uint32_t*       hsp = hsw + p * 2304;
        const uint32_t* hq  = hsw + (p ^ 1) * 2304;

        // phase A: reads w0a(c), w1a(c-1), hq; refills w0b(c), w1b(c-1)
        CP_WAIT0(); __syncthreads();
        load_w1_half(sb, c - 1, 1, tid);
        load_w0_half(sb, c, 1, tid);
        CP_COMMIT();
        float c1[4][4] = {};
        g1_steps<0, 6>(c1, xsw, w0sw, m1, n1, r, q);
        g2_steps<0, 2>(acc2, hq, w1sw, m2, n2, r, q);

        // phase B: reads w0b(c), w1b(c-1); refills w0a(c+1), w1a(c)
        CP_WAIT0(); __syncthreads();
        if (c + 1 <= 15) load_w0_half(sb, c + 1, 0, tid);
        load_w1_half(sb, c, 0, tid);
        CP_COMMIT();
        g1_steps<6, 12>(c1, xsw, w0sw, m1, n1, r, q);
        g2_steps<2, 4>(acc2, hq, w1sw, m2, n2, r, q);
        convert_store(c1, hsp, b0s, c, m1, n1, r, q);
    }

    // ===== peel c = 16 (GEMM2(15) only; h(15) in hs[1]) =====
    {
        const uint32_t* hq = hsw + 2304;
        CP_WAIT0(); __syncthreads();
        load_w1_half(sb, 15, 1, tid);
        CP_COMMIT();
        g2_steps<0, 2>(acc2, hq, w1sw, m2, n2, r, q);

        CP_WAIT0(); __syncthreads();
        g2_steps<2, 4>(acc2, hq, w1sw, m2, n2, r, q);
    }

    // ---- epilogue: +b1, relu, store ----
    #pragma unroll
    for (int j = 0; j < 8; j++) {
        int n = n2 + j * 8 + q * 2;
        float bb0 = b1s[n], bb1 = b1s[n + 1];
        #pragma unroll
        for (int f = 0; f < 2; f++) {
            const int rowg = slice * 128 + tokbase + m2 + f * 16 + r;
            float2 o0, o1;
            o0.x = fmaxf(acc2[j * 2 + f][0] + bb0, 0.f);
            o0.y = fmaxf(acc2[j * 2 + f][1] + bb1, 0.f);
            o1.x = fmaxf(acc2[j * 2 + f][2] + bb0, 0.f);
            o1.y = fmaxf(acc2[j * 2 + f][3] + bb1, 0.f);
            *(float2*)(out + (size_t)rowg * 256 + n)       = o0;
            *(float2*)(out + (size_t)(rowg + 8) * 256 + n) = o1;
        }
    }
}

extern "C" void kernel_launch(void* const* d_in, const int* in_sizes, int n_in,
                              void* d_out, int out_size)
{
    const float* x  = (const float*)d_in[0];
    const float* W0 = (const float*)d_in[1];
    const float* b0 = (const float*)d_in[2];
    const float* W1 = (const float*)d_in[3];
    const float* b1 = (const float*)d_in[4];
    float* out = (float*)d_out;

    static bool configured = false;
    if (!configured) {
        cudaFuncSetAttribute(mlp_kernel,
                             cudaFuncAttributeMaxDynamicSharedMemorySize, SM_TOTAL);
        configured = true;
    }
    prep_kernel<<<256, 256>>>(W0, W1);
    mlp_kernel<<<3072, 256, SM_TOTAL>>>(x, b0, b1, out);
}

// round 13
// speedup vs baseline: 1.1472x; 1.1472x over previous
#include <cuda_runtime.h>
#include <cuda_fp16.h>
#include <cstdint>

// Fused 2-layer MLP, pure fp16 mma.sync, 2 CTAs/SM (R11 structure) with
// ldmatrix (LDSM.x4) fragment loads: 240 LDS.32 -> 60 LDSM.x4 per warp/chunk.
//   out = relu(relu(X@W0+b0)@W1+b1); rel_err ~4.2e-4 (validated R9/R11).

#define K1   192
#define HID  1024
#define EMB  256
#define NCH  16

#define XS_W  100     // words/row Xs (100%32=4 -> conflict-free LDSM phases)
#define W0S_W 100
#define HS_W  36
#define W1S_W 36

// smem byte offsets (total 100 KB -> 2 CTAs/SM)
#define SM_B0S 0
#define SM_B1S 4096
#define SM_XS  5120                   // 64*400  = 25600
#define SM_W0S 30720                  // 64*400  = 25600
#define SM_HS  56320                  // 64*144  = 9216
#define SM_W1S 65536                  // 256*144 = 36864
#define SM_TOTAL 102400

__device__ __align__(16) __half g_B1[HID * K1];     // W0^T [n][k]
__device__ __align__(16) __half g_B2[EMB * HID];    // W1^T [n][k]

__device__ __forceinline__ void cpa16(uint32_t dst, const void* src) {
    asm volatile("cp.async.cg.shared.global [%0], [%1], 16;" :: "r"(dst), "l"(src) : "memory");
}
#define CP_COMMIT() asm volatile("cp.async.commit_group;" ::: "memory")
#define CP_WAIT1()  asm volatile("cp.async.wait_group 1;" ::: "memory")
#define CP_WAIT0()  asm volatile("cp.async.wait_group 0;" ::: "memory")

__device__ __forceinline__ uint32_t smem_u32(const void* p) {
    uint32_t a;
    asm("{ .reg .u64 t; cvta.to.shared.u64 t, %1; cvt.u32.u64 %0, t; }" : "=r"(a) : "l"(p));
    return a;
}

__device__ __forceinline__ void ldsm4(uint32_t& r0, uint32_t& r1, uint32_t& r2,
                                      uint32_t& r3, uint32_t addr)
{
    asm volatile("ldmatrix.sync.aligned.m8n8.x4.shared.b16 {%0,%1,%2,%3}, [%4];"
        : "=r"(r0), "=r"(r1), "=r"(r2), "=r"(r3) : "r"(addr));
}

__device__ __forceinline__ void mma16816(float* c,
    uint32_t a0, uint32_t a1, uint32_t a2, uint32_t a3, uint32_t b0, uint32_t b1)
{
    asm volatile("mma.sync.aligned.m16n8k16.row.col.f32.f16.f16.f32 "
        "{%0,%1,%2,%3}, {%4,%5,%6,%7}, {%8,%9}, {%0,%1,%2,%3};"
        : "+f"(c[0]), "+f"(c[1]), "+f"(c[2]), "+f"(c[3])
        : "r"(a0), "r"(a1), "r"(a2), "r"(a3), "r"(b0), "r"(b1));
}

__device__ __forceinline__ uint32_t pack2(float x, float y) {
    __half2 h = __halves2half2(__float2half_rn(x), __float2half_rn(y));
    return *(uint32_t*)&h;
}

// ---------------- weight prep: fp16, transposed to [n][k] ----------------
__global__ void prep_kernel(const float* __restrict__ W0, const float* __restrict__ W1) {
    int stride = gridDim.x * blockDim.x;
    int t0 = blockIdx.x * blockDim.x + threadIdx.x;
    for (int i = t0; i < HID * K1; i += stride) {
        int n = i / K1, k = i % K1;
        g_B1[n * K1 + k] = __float2half_rn(W0[k * HID + n]);
    }
    for (int i = t0; i < EMB * HID; i += stride) {
        int n = i / HID, k = i % HID;
        g_B2[n * HID + k] = __float2half_rn(W1[k * EMB + n]);
    }
}

// ---------------- chunk loaders (256 threads) ----------------
__device__ __forceinline__ void load_w0(uint32_t sb, int c, int tid) {
    const __half* base = g_B1 + (size_t)c * 64 * K1;
    #pragma unroll
    for (int i = tid; i < 1536; i += 256) {           // 64 rows x 24 x 16B
        int n = i / 24, u = i % 24;
        cpa16(sb + SM_W0S + n * 400 + u * 16, base + n * K1 + u * 8);
    }
    CP_COMMIT();
}
__device__ __forceinline__ void load_w1(uint32_t sb, int c, int tid) {
    const __half* base = g_B2 + c * 64;
    #pragma unroll
    for (int i = tid; i < 2048; i += 256) {           // 256 rows x 8 x 16B
        int n = i / 8, u = i % 8;
        cpa16(sb + SM_W1S + n * 144 + u * 16, base + n * HID + u * 8);
    }
    CP_COMMIT();
}

// ---------------- main fused kernel ----------------
__global__ void __launch_bounds__(256, 2)
mlp_kernel(const float* __restrict__ x, const float* __restrict__ b0,
           const float* __restrict__ b1, float* __restrict__ out)
{
    extern __shared__ char smem[];
    const uint32_t sb = smem_u32(smem);
    const int tid  = threadIdx.x;
    const int lane = tid & 31;
    const int w    = tid >> 5;
    const int r    = lane >> 2;
    const int q    = lane & 3;

    // GEMM1 warp tile 16x32; GEMM2 warp tile 32x64
    const int m1 = (w >> 1) * 16;
    const int n1 = (w & 1) * 32;
    const int m2 = (w >> 2) * 32;
    const int n2 = (w & 3) * 64;

    const int slice   = blockIdx.x >> 1;
    const int tokbase = (blockIdx.x & 1) * 64;

    uint32_t* xsw = (uint32_t*)(smem + SM_XS);
    uint32_t* hsw = (uint32_t*)(smem + SM_HS);
    float*    b0s = (float*)(smem + SM_B0S);
    float*    b1s = (float*)(smem + SM_B1S);

    // LDSM per-lane base addresses (bytes, shared space)
    // A (16-row fragments): rows via lane&15, k-half (+16B) via lane>>4
    const uint32_t baseA1 = sb + SM_XS
        + (uint32_t)(((m1 + (lane & 15)) * XS_W + ((lane >> 4) << 2)) * 4);
    const uint32_t baseA2 = sb + SM_HS
        + (uint32_t)(((m2 + (lane & 15)) * HS_W + ((lane >> 4) << 2)) * 4);
    // B (8-row matrix pairs): n-row via lane&7 (+8 rows for upper pair),
    // k-half (+16B) via (lane>>3)&1
    const uint32_t baseB1 = sb + SM_W0S
        + (uint32_t)(((n1 + (lane & 7) + ((lane >> 4) << 3)) * W0S_W
                      + (((lane >> 3) & 1) << 2)) * 4);
    const uint32_t baseB2 = sb + SM_W1S
        + (uint32_t)(((n2 + (lane & 7) + ((lane >> 4) << 3)) * W1S_W
                      + (((lane >> 3) & 1) << 2)) * 4);

    // prefetch chunk 0 weights
    load_w0(sb, 0, tid);
    load_w1(sb, 0, tid);

    // X slice -> Xs (fp16, 96 words per row)
    {
        const float2* x2 = (const float2*)(x + (size_t)slice * 24576);
        #pragma unroll 4
        for (int i = tid; i < 6144; i += 256) {
            int m = i / 96, u = i % 96;
            int ch = u >> 5, bp = u & 31;
            float2 v = x2[(ch * 8192 + (tokbase + m) * 64) / 2 + bp];
            xsw[m * XS_W + ch * 32 + bp] = pack2(v.x, v.y);
        }
        for (int i = tid; i < 1024; i += 256) b0s[i] = b0[i];
        for (int i = tid; i < 256;  i += 256) b1s[i] = b1[i];
    }

    float acc2[16][4];
    #pragma unroll
    for (int j = 0; j < 16; j++)
        #pragma unroll
        for (int e = 0; e < 4; e++) acc2[j][e] = 0.0f;

    for (int c = 0; c < NCH; c++) {
        CP_WAIT1();                  // w0(c) resident (w1(c) may be in flight)
        __syncthreads();

        // ---- GEMM1: c1[16x32 per warp], k = 192, LDSM fragments ----
        float c1[4][4];
        #pragma unroll
        for (int j = 0; j < 4; j++)
            #pragma unroll
            for (int e = 0; e < 4; e++) c1[j][e] = 0.0f;

        #pragma unroll 4
        for (int kk = 0; kk < 12; kk++) {
            const uint32_t ko = kk * 32;
            uint32_t a0, a1, a2, a3;
            ldsm4(a0, a1, a2, a3, baseA1 + ko);
            uint32_t b00, b01, b10, b11, b20, b21, b30, b31;
            ldsm4(b00, b01, b10, b11, baseB1 + ko);          // j = 0,1
            ldsm4(b20, b21, b30, b31, baseB1 + 6400 + ko);   // j = 2,3 (+16 rows)
            mma16816(c1[0], a0, a1, a2, a3, b00, b01);
            mma16816(c1[1], a0, a1, a2, a3, b10, b11);
            mma16816(c1[2], a0, a1, a2, a3, b20, b21);
            mma16816(c1[3], a0, a1, a2, a3, b30, b31);
        }

        // ---- bias + relu + fp16 -> hs ----
        {
            const int hb = c * 64;
            #pragma unroll
            for (int j = 0; j < 4; j++) {
                int n = n1 + j * 8 + q * 2;
                float bb0 = b0s[hb + n], bb1 = b0s[hb + n + 1];
                float v0 = fmaxf(c1[j][0] + bb0, 0.f);
                float v1 = fmaxf(c1[j][1] + bb1, 0.f);
                float v2 = fmaxf(c1[j][2] + bb0, 0.f);
                float v3 = fmaxf(c1[j][3] + bb1, 0.f);
                hsw[(m1 + r) * HS_W + (n >> 1)]     = pack2(v0, v1);
                hsw[(m1 + r + 8) * HS_W + (n >> 1)] = pack2(v2, v3);
            }
        }
        __syncthreads();             // w0s free, hs published
        if (c + 1 < NCH) load_w0(sb, c + 1, tid);

        if (c + 1 < NCH) { CP_WAIT1(); } else { CP_WAIT0(); }  // w1(c) resident
        __syncthreads();

        // ---- GEMM2: acc2[32x64 per warp] += hs @ w1s, LDSM fragments ----
        #pragma unroll
        for (int kk = 0; kk < 4; kk++) {
            const uint32_t ko = kk * 32;
            uint32_t a[2][4];
            ldsm4(a[0][0], a[0][1], a[0][2], a[0][3], baseA2 + ko);          // f=0
            ldsm4(a[1][0], a[1][1], a[1][2], a[1][3], baseA2 + 2304 + ko);   // f=1
            #pragma unroll
            for (int jp = 0; jp < 4; jp++) {
                uint32_t c0, c1_, c2, c3;
                ldsm4(c0, c1_, c2, c3, baseB2 + jp * 2304 + ko);  // j=2jp, 2jp+1
                const int j0 = jp * 2;
                #pragma unroll
                for (int f = 0; f < 2; f++) {
                    mma16816(acc2[j0 * 2 + f],       a[f][0], a[f][1], a[f][2], a[f][3], c0, c1_);
                    mma16816(acc2[(j0 + 1) * 2 + f], a[f][0], a[f][1], a[f][2], a[f][3], c2, c3);
                }
            }
        }
        __syncthreads();             // w1s + hs free
        if (c + 1 < NCH) load_w1(sb, c + 1, tid);
    }

    // ---- epilogue: +b1, relu, store ----
    #pragma unroll
    for (int j = 0; j < 8; j++) {
        int n = n2 + j * 8 + q * 2;
        float bb0 = b1s[n], bb1 = b1s[n + 1];
        #pragma unroll
        for (int f = 0; f < 2; f++) {
            const int rowg = slice * 128 + tokbase + m2 + f * 16 + r;
            float2 o0, o1;
            o0.x = fmaxf(acc2[j * 2 + f][0] + bb0, 0.f);
            o0.y = fmaxf(acc2[j * 2 + f][1] + bb1, 0.f);
            o1.x = fmaxf(acc2[j * 2 + f][2] + bb0, 0.f);
            o1.y = fmaxf(acc2[j * 2 + f][3] + bb1, 0.f);
            *(float2*)(out + (size_t)rowg * 256 + n)       = o0;
            *(float2*)(out + (size_t)(rowg + 8) * 256 + n) = o1;
        }
    }
}

extern "C" void kernel_launch(void* const* d_in, const int* in_sizes, int n_in,
                              void* d_out, int out_size)
{
    const float* x  = (const float*)d_in[0];
    const float* W0 = (const float*)d_in[1];
    const float* b0 = (const float*)d_in[2];
    const float* W1 = (const float*)d_in[3];
    const float* b1 = (const float*)d_in[4];
    float* out = (float*)d_out;

    static bool configured = false;
    if (!configured) {
        cudaFuncSetAttribute(mlp_kernel,
                             cudaFuncAttributeMaxDynamicSharedMemorySize, SM_TOTAL);
        configured = true;
    }
    prep_kernel<<<256, 256>>>(W0, W1);
    mlp_kernel<<<3072, 256, SM_TOTAL>>>(x, b0, b1, out);
}